// round 2
// baseline (speedup 1.0000x reference)
#include <cuda_runtime.h>

#define W_DIM 1024
#define F_DIM 512
#define NHD   64
#define NBC   8
#define QK_SCALE 0.044194173824159216f  // 1/sqrt(512)

__device__ float g_P[NBC * F_DIM * W_DIM];  // projection (V source)
__device__ float g_Q[NBC * F_DIM * W_DIM];  // roped Q (== roped K)
__device__ float g_A[NBC * F_DIM * W_DIM];  // attention output

// ---------------------------------------------------------------------------
// cp.async helpers
// ---------------------------------------------------------------------------
__device__ __forceinline__ void cp_async16(void* smem_dst, const void* gsrc) {
    unsigned sdst = (unsigned)__cvta_generic_to_shared(smem_dst);
    asm volatile("cp.async.ca.shared.global [%0], [%1], 16;\n" :: "r"(sdst), "l"(gsrc));
}
#define CP_COMMIT() asm volatile("cp.async.commit_group;\n" ::)
#define CP_WAIT1()  asm volatile("cp.async.wait_group 1;\n" ::)
#define CP_WAIT0()  asm volatile("cp.async.wait_group 0;\n" ::)

// ---------------------------------------------------------------------------
// GEMM: Out[bc][g][w] = sum_h Wm[c][g][h] * X[bc][h][w]
// 128x128 tile, BK=16, cp.async double buffer, 8x8 micro.
// mode 0: X = Xin,  write g_P raw + g_Q roped (fp = freqs table source)
// mode 1: X = g_A,  write Op
// Dynamic smem: As[2][128*20] | Bs[2][16*128] | csT[2048] float2 (mode 0 only)
// ---------------------------------------------------------------------------
__global__ __launch_bounds__(256, 2) void gemm_kernel(const float* __restrict__ Wm,
                                                      const float* __restrict__ Xin,
                                                      float* __restrict__ Op,
                                                      const float* __restrict__ fp,
                                                      int mode) {
    extern __shared__ float sm[];
    float*  As  = sm;                       // 2 * 128*20 = 5120 floats
    float*  Bs  = sm + 5120;                // 2 * 16*128 = 4096 floats
    float2* csT = (float2*)(sm + 9216);     // 2048 float2 (mode 0)

    const float* X = (mode == 0) ? Xin : g_A;
    const int bc = blockIdx.z;
    const float* Wb = Wm + (size_t)(bc & 1) * (F_DIM * F_DIM);
    const float* Xb = X  + (size_t)bc * (F_DIM * W_DIM);

    const int g0 = blockIdx.y * 128;
    const int w0 = blockIdx.x * 128;
    const int tid = threadIdx.x;
    const int ty = tid >> 4, tx = tid & 15;
    const int lg = tid >> 2, lw = tid & 3;     // A load: rows lg, lg+64, cols lw*4
    const int lk = tid >> 4, lx = tid & 15;    // B load: row lk, cols lx*4, +64

    // Prologue: issue first tile, then fill rope table (overlaps load latency)
    {
        float* A0 = As;
        float* B0 = Bs;
        cp_async16(&A0[lg * 20 + lw * 4],        &Wb[(size_t)(g0 + lg) * F_DIM + lw * 4]);
        cp_async16(&A0[(lg + 64) * 20 + lw * 4], &Wb[(size_t)(g0 + lg + 64) * F_DIM + lw * 4]);
        cp_async16(&B0[lk * 128 + lx * 4],       &Xb[(size_t)lk * W_DIM + w0 + lx * 4]);
        cp_async16(&B0[lk * 128 + lx * 4 + 64],  &Xb[(size_t)lk * W_DIM + w0 + lx * 4 + 64]);
        CP_COMMIT();
    }
    if (mode == 0) {
        for (int t = tid; t < 2048; t += 256) {
            int wl = t >> 4, j = t & 15;
            float sv, cv;
            sincosf((float)(w0 + wl) * fp[j], &sv, &cv);
            csT[t] = make_float2(cv, sv);
        }
    }

    float acc[8][8];
#pragma unroll
    for (int i = 0; i < 8; i++)
#pragma unroll
        for (int j = 0; j < 8; j++) acc[i][j] = 0.f;

    for (int t = 0; t < 32; t++) {
        const int buf = t & 1;
        if (t < 31) {
            const int k0 = (t + 1) * 16;
            float* An = As + (buf ^ 1) * 2560;
            float* Bn = Bs + (buf ^ 1) * 2048;
            cp_async16(&An[lg * 20 + lw * 4],        &Wb[(size_t)(g0 + lg) * F_DIM + k0 + lw * 4]);
            cp_async16(&An[(lg + 64) * 20 + lw * 4], &Wb[(size_t)(g0 + lg + 64) * F_DIM + k0 + lw * 4]);
            cp_async16(&Bn[lk * 128 + lx * 4],       &Xb[(size_t)(k0 + lk) * W_DIM + w0 + lx * 4]);
            cp_async16(&Bn[lk * 128 + lx * 4 + 64],  &Xb[(size_t)(k0 + lk) * W_DIM + w0 + lx * 4 + 64]);
            CP_COMMIT();
            CP_WAIT1();
        } else {
            CP_WAIT0();
        }
        __syncthreads();
        const float* Ab = As + buf * 2560;
        const float* Bb = Bs + buf * 2048;
#pragma unroll
        for (int kk = 0; kk < 16; kk++) {
            float a[8], b[8];
#pragma unroll
            for (int i = 0; i < 8; i++) a[i] = Ab[(ty * 8 + i) * 20 + kk];
            *(float4*)&b[0] = *(const float4*)&Bb[kk * 128 + tx * 8];
            *(float4*)&b[4] = *(const float4*)&Bb[kk * 128 + tx * 8 + 4];
#pragma unroll
            for (int i = 0; i < 8; i++)
#pragma unroll
                for (int j = 0; j < 8; j++) acc[i][j] += a[i] * b[j];
        }
        __syncthreads();
    }

    if (mode == 1) {
#pragma unroll
        for (int i = 0; i < 8; i++) {
            float* dst = &Op[(size_t)bc * F_DIM * W_DIM + (size_t)(g0 + ty * 8 + i) * W_DIM + w0 + tx * 8];
            *(float4*)dst       = make_float4(acc[i][0], acc[i][1], acc[i][2], acc[i][3]);
            *(float4*)(dst + 4) = make_float4(acc[i][4], acc[i][5], acc[i][6], acc[i][7]);
        }
    } else {
        // fused RoPE epilogue: rows (even, odd) pairs live in this thread
        float* Pb = g_P + (size_t)bc * F_DIM * W_DIM;
        float* Qb = g_Q + (size_t)bc * F_DIM * W_DIM;
#pragma unroll
        for (int i = 0; i < 8; i += 2) {
            const int r0 = ty * 8 + i;          // g0 is a multiple of 64 -> hd = r0 & 63
            const int hd = r0 & 63;
            float q0[8], q1[8];
            if (hd < 32) {
                const int j = hd >> 1;
#pragma unroll
                for (int jc = 0; jc < 8; jc++) {
                    float2 cs = csT[(tx * 8 + jc) * 16 + j];
                    q0[jc] = acc[i][jc]     * cs.x - acc[i + 1][jc] * cs.y;
                    q1[jc] = acc[i + 1][jc] * cs.x + acc[i][jc]     * cs.y;
                }
            } else {
#pragma unroll
                for (int jc = 0; jc < 8; jc++) { q0[jc] = acc[i][jc]; q1[jc] = acc[i + 1][jc]; }
            }
            float* p0 = &Pb[(size_t)(g0 + r0) * W_DIM + w0 + tx * 8];
            float* p1 = p0 + W_DIM;
            *(float4*)p0       = make_float4(acc[i][0], acc[i][1], acc[i][2], acc[i][3]);
            *(float4*)(p0 + 4) = make_float4(acc[i][4], acc[i][5], acc[i][6], acc[i][7]);
            *(float4*)p1       = make_float4(acc[i+1][0], acc[i+1][1], acc[i+1][2], acc[i+1][3]);
            *(float4*)(p1 + 4) = make_float4(acc[i+1][4], acc[i+1][5], acc[i+1][6], acc[i+1][7]);
            float* t0 = &Qb[(size_t)(g0 + r0) * W_DIM + w0 + tx * 8];
            float* t1 = t0 + W_DIM;
            *(float4*)t0       = make_float4(q0[0], q0[1], q0[2], q0[3]);
            *(float4*)(t0 + 4) = make_float4(q0[4], q0[5], q0[6], q0[7]);
            *(float4*)t1       = make_float4(q1[0], q1[1], q1[2], q1[3]);
            *(float4*)(t1 + 4) = make_float4(q1[4], q1[5], q1[6], q1[7]);
        }
    }
}

// ---------------------------------------------------------------------------
// Flash attention fp32, K == Q. 128 queries x 128-key tiles, 256 thr, 8x8 micro.
// smem (floats): Qs[64*128] Ks[64*128] Vs[128*64 swz] Ss[128*132] M/L/A[128]
// = 41856 floats = 167424 B -> 1 CTA/SM. grid = (8 q-tiles, 64 head-batches)
// ---------------------------------------------------------------------------
__global__ __launch_bounds__(256) void attn_kernel() {
    extern __shared__ float sm[];
    float* Qs   = sm;              // [d][q]  8192
    float* Ks   = sm + 8192;       // [d][k]  8192
    float* Vs   = sm + 16384;      // [k][d]  8192, 16B-granule xor swizzle
    float* Ss   = sm + 24576;      // [q][k]  128*132
    float* Mrow = sm + 41472;
    float* Lrow = sm + 41600;
    float* Arow = sm + 41728;

    const int tid = threadIdx.x;
    const int q0  = blockIdx.x * 128;
    const int bcn = blockIdx.y;

    const float* Qb = g_Q + (size_t)bcn * (NHD * W_DIM);
    const float* Vb = g_P + (size_t)bcn * (NHD * W_DIM);
    float*       Ab = g_A + (size_t)bcn * (NHD * W_DIM);

    for (int i = tid; i < 8192; i += 256) {
        int d = i >> 7, q = i & 127;
        Qs[i] = Qb[(size_t)d * W_DIM + q0 + q] * QK_SCALE;
    }
    if (tid < 128) { Mrow[tid] = -1e30f; Lrow[tid] = 0.f; }

    const int ty = tid >> 4, tx = tid & 15;     // q-group / k(d)-group
    const int qq = tid >> 1, sub = tid & 1;     // softmax: 2 lanes per q row
    float o[8][8];
#pragma unroll
    for (int i = 0; i < 8; i++)
#pragma unroll
        for (int j = 0; j < 8; j++) o[i][j] = 0.f;

    for (int kt = 0; kt < 8; kt++) {
        const int k0 = kt * 128;
        __syncthreads();
        for (int i = tid; i < 8192; i += 256) {
            int d = i >> 7, k = i & 127;
            Ks[i] = Qb[(size_t)d * W_DIM + k0 + k];
            float vv = Vb[(size_t)d * W_DIM + k0 + k];
            Vs[(k << 6) + ((((d >> 2) ^ (k & 15)) << 2) | (d & 3))] = vv;
        }
        __syncthreads();

        // scores
        float s[8][8];
#pragma unroll
        for (int i = 0; i < 8; i++)
#pragma unroll
            for (int j = 0; j < 8; j++) s[i][j] = 0.f;
#pragma unroll 8
        for (int d = 0; d < 64; d++) {
            float a[8], b[8];
            *(float4*)&a[0] = *(float4*)&Qs[(d << 7) + (ty << 3)];
            *(float4*)&a[4] = *(float4*)&Qs[(d << 7) + (ty << 3) + 4];
            *(float4*)&b[0] = *(float4*)&Ks[(d << 7) + (tx << 3)];
            *(float4*)&b[4] = *(float4*)&Ks[(d << 7) + (tx << 3) + 4];
#pragma unroll
            for (int i = 0; i < 8; i++)
#pragma unroll
                for (int j = 0; j < 8; j++) s[i][j] += a[i] * b[j];
        }
#pragma unroll
        for (int i = 0; i < 8; i++) {   // Ss[q][k]
            *(float4*)&Ss[(ty * 8 + i) * 132 + tx * 8]     = make_float4(s[i][0], s[i][1], s[i][2], s[i][3]);
            *(float4*)&Ss[(ty * 8 + i) * 132 + tx * 8 + 4] = make_float4(s[i][4], s[i][5], s[i][6], s[i][7]);
        }
        __syncthreads();

        // online softmax (2 lanes per query row)
        float mx = -1e30f;
#pragma unroll 16
        for (int ki = sub; ki < 128; ki += 2) mx = fmaxf(mx, Ss[qq * 132 + ki]);
        mx = fmaxf(mx, __shfl_xor_sync(0xffffffffu, mx, 1));
        float m_old = Mrow[qq];
        float m_new = fmaxf(m_old, mx);
        float ssum = 0.f;
#pragma unroll 16
        for (int ki = sub; ki < 128; ki += 2) {
            float p = __expf(Ss[qq * 132 + ki] - m_new);
            Ss[qq * 132 + ki] = p;
            ssum += p;
        }
        ssum += __shfl_xor_sync(0xffffffffu, ssum, 1);
        if (sub == 0) {
            float al = __expf(m_old - m_new);
            Arow[qq] = al;
            Lrow[qq] = Lrow[qq] * al + ssum;
            Mrow[qq] = m_new;
        }
        __syncthreads();

        // rescale + PV
        float al[8];
#pragma unroll
        for (int i = 0; i < 8; i++) al[i] = Arow[ty * 8 + i];
#pragma unroll
        for (int i = 0; i < 8; i++)
#pragma unroll
            for (int j = 0; j < 8; j++) o[i][j] *= al[i];
#pragma unroll 4
        for (int ki = 0; ki < 128; ki++) {
            const int m = ki & 15;
            float a[8], b[8];
#pragma unroll
            for (int i = 0; i < 8; i++) a[i] = Ss[(ty * 8 + i) * 132 + ki];
            *(float4*)&b[0] = *(float4*)&Vs[(ki << 6) + (((2 * tx)     ^ m) << 2)];
            *(float4*)&b[4] = *(float4*)&Vs[(ki << 6) + (((2 * tx + 1) ^ m) << 2)];
#pragma unroll
            for (int i = 0; i < 8; i++)
#pragma unroll
                for (int j = 0; j < 8; j++) o[i][j] += a[i] * b[j];
        }
    }

    __syncthreads();
    float inv[8];
#pragma unroll
    for (int i = 0; i < 8; i++) inv[i] = 1.f / Lrow[ty * 8 + i];
#pragma unroll
    for (int j = 0; j < 8; j++) {   // stage (d, q) into Ss
        *(float4*)&Ss[(tx * 8 + j) * 132 + ty * 8] =
            make_float4(o[0][j] * inv[0], o[1][j] * inv[1], o[2][j] * inv[2], o[3][j] * inv[3]);
        *(float4*)&Ss[(tx * 8 + j) * 132 + ty * 8 + 4] =
            make_float4(o[4][j] * inv[4], o[5][j] * inv[5], o[6][j] * inv[6], o[7][j] * inv[7]);
    }
    __syncthreads();
    for (int i = tid; i < 8192; i += 256) {
        int d = i >> 7, q = i & 127;
        Ab[(size_t)d * W_DIM + q0 + q] = Ss[d * 132 + q];
    }
}

// ---------------------------------------------------------------------------
// Launch. Inputs: x, wq, wk, wv, wo, freqs_param (wk/wv dead in reference).
// ---------------------------------------------------------------------------
extern "C" void kernel_launch(void* const* d_in, const int* in_sizes, int n_in,
                              void* d_out, int out_size) {
    (void)in_sizes; (void)n_in; (void)out_size;
    const float* x  = (const float*)d_in[0];
    const float* wq = (const float*)d_in[1];
    const float* wo = (const float*)d_in[4];
    const float* fp = (const float*)d_in[5];
    float* out = (float*)d_out;

    cudaFuncSetAttribute(gemm_kernel, cudaFuncAttributeMaxDynamicSharedMemorySize, 53248);
    cudaFuncSetAttribute(attn_kernel, cudaFuncAttributeMaxDynamicSharedMemorySize, 167424);

    dim3 gg(8, 4, 8);
    gemm_kernel<<<gg, 256, 53248>>>(wq, x, nullptr, fp, 0);   // P + roped Q (fused RoPE)
    attn_kernel<<<dim3(8, 64), 256, 167424>>>();              // A = softmax(QQ^T/√F) V
    gemm_kernel<<<gg, 256, 36864>>>(wo, nullptr, out, nullptr, 1);  // out = Wo @ A
}

// round 3
// speedup vs baseline: 2.3127x; 2.3127x over previous
#include <cuda_runtime.h>

#define W_DIM 1024
#define F_DIM 512
#define NHD   64
#define NBC   8
#define QK_SCALE 0.044194173824159216f  // 1/sqrt(512)

__device__ float g_P[NBC * F_DIM * W_DIM];  // projection (V source)
__device__ float g_Q[NBC * F_DIM * W_DIM];  // roped Q (== roped K)
__device__ float g_A[NBC * F_DIM * W_DIM];  // attention output

// ---------------------------------------------------------------------------
// helpers
// ---------------------------------------------------------------------------
__device__ __forceinline__ void cp_async16(void* smem_dst, const void* gsrc) {
    unsigned sdst = (unsigned)__cvta_generic_to_shared(smem_dst);
    asm volatile("cp.async.ca.shared.global [%0], [%1], 16;\n" :: "r"(sdst), "l"(gsrc));
}
#define CP_COMMIT() asm volatile("cp.async.commit_group;\n" ::)
#define CP_WAIT1()  asm volatile("cp.async.wait_group 1;\n" ::)
#define CP_WAIT0()  asm volatile("cp.async.wait_group 0;\n" ::)

__device__ __forceinline__ float f2tf(float f) {
    unsigned r;
    asm("cvt.rna.tf32.f32 %0, %1;" : "=r"(r) : "f"(f));
    return __uint_as_float(r);
}
__device__ __forceinline__ void mma_tf32(float c[4], unsigned a0, unsigned a1,
                                         unsigned a2, unsigned a3,
                                         unsigned b0, unsigned b1) {
    asm volatile("mma.sync.aligned.m16n8k8.row.col.f32.tf32.tf32.f32 "
                 "{%0,%1,%2,%3},{%4,%5,%6,%7},{%8,%9},{%0,%1,%2,%3};"
                 : "+f"(c[0]), "+f"(c[1]), "+f"(c[2]), "+f"(c[3])
                 : "r"(a0), "r"(a1), "r"(a2), "r"(a3), "r"(b0), "r"(b1));
}
#define SWZ(d, t) ((((((d) >> 2) ^ ((t) & 15)) << 2)) | ((d) & 3))

// ---------------------------------------------------------------------------
// GEMM (fp32 SIMT, cp.async double buffer) — unchanged from R2 (passing).
// mode 0: X=Xin, write g_P raw + g_Q roped.  mode 1: X=g_A, write Op.
// ---------------------------------------------------------------------------
__global__ __launch_bounds__(256, 2) void gemm_kernel(const float* __restrict__ Wm,
                                                      const float* __restrict__ Xin,
                                                      float* __restrict__ Op,
                                                      const float* __restrict__ fp,
                                                      int mode) {
    extern __shared__ float sm[];
    float*  As  = sm;                       // 2 * 128*20
    float*  Bs  = sm + 5120;                // 2 * 16*128
    float2* csT = (float2*)(sm + 9216);     // 2048 float2 (mode 0)

    const float* X = (mode == 0) ? Xin : g_A;
    const int bc = blockIdx.z;
    const float* Wb = Wm + (size_t)(bc & 1) * (F_DIM * F_DIM);
    const float* Xb = X  + (size_t)bc * (F_DIM * W_DIM);

    const int g0 = blockIdx.y * 128;
    const int w0 = blockIdx.x * 128;
    const int tid = threadIdx.x;
    const int ty = tid >> 4, tx = tid & 15;
    const int lg = tid >> 2, lw = tid & 3;
    const int lk = tid >> 4, lx = tid & 15;

    {
        cp_async16(&As[lg * 20 + lw * 4],        &Wb[(size_t)(g0 + lg) * F_DIM + lw * 4]);
        cp_async16(&As[(lg + 64) * 20 + lw * 4], &Wb[(size_t)(g0 + lg + 64) * F_DIM + lw * 4]);
        cp_async16(&Bs[lk * 128 + lx * 4],       &Xb[(size_t)lk * W_DIM + w0 + lx * 4]);
        cp_async16(&Bs[lk * 128 + lx * 4 + 64],  &Xb[(size_t)lk * W_DIM + w0 + lx * 4 + 64]);
        CP_COMMIT();
    }
    if (mode == 0) {
        for (int t = tid; t < 2048; t += 256) {
            int wl = t >> 4, j = t & 15;
            float sv, cv;
            sincosf((float)(w0 + wl) * fp[j], &sv, &cv);
            csT[t] = make_float2(cv, sv);
        }
    }

    float acc[8][8];
#pragma unroll
    for (int i = 0; i < 8; i++)
#pragma unroll
        for (int j = 0; j < 8; j++) acc[i][j] = 0.f;

    for (int t = 0; t < 32; t++) {
        const int buf = t & 1;
        if (t < 31) {
            const int k0 = (t + 1) * 16;
            float* An = As + (buf ^ 1) * 2560;
            float* Bn = Bs + (buf ^ 1) * 2048;
            cp_async16(&An[lg * 20 + lw * 4],        &Wb[(size_t)(g0 + lg) * F_DIM + k0 + lw * 4]);
            cp_async16(&An[(lg + 64) * 20 + lw * 4], &Wb[(size_t)(g0 + lg + 64) * F_DIM + k0 + lw * 4]);
            cp_async16(&Bn[lk * 128 + lx * 4],       &Xb[(size_t)(k0 + lk) * W_DIM + w0 + lx * 4]);
            cp_async16(&Bn[lk * 128 + lx * 4 + 64],  &Xb[(size_t)(k0 + lk) * W_DIM + w0 + lx * 4 + 64]);
            CP_COMMIT();
            CP_WAIT1();
        } else {
            CP_WAIT0();
        }
        __syncthreads();
        const float* Ab = As + buf * 2560;
        const float* Bb = Bs + buf * 2048;
#pragma unroll
        for (int kk = 0; kk < 16; kk++) {
            float a[8], b[8];
#pragma unroll
            for (int i = 0; i < 8; i++) a[i] = Ab[(ty * 8 + i) * 20 + kk];
            *(float4*)&b[0] = *(const float4*)&Bb[kk * 128 + tx * 8];
            *(float4*)&b[4] = *(const float4*)&Bb[kk * 128 + tx * 8 + 4];
#pragma unroll
            for (int i = 0; i < 8; i++)
#pragma unroll
                for (int j = 0; j < 8; j++) acc[i][j] += a[i] * b[j];
        }
        __syncthreads();
    }

    if (mode == 1) {
#pragma unroll
        for (int i = 0; i < 8; i++) {
            float* dst = &Op[(size_t)bc * F_DIM * W_DIM + (size_t)(g0 + ty * 8 + i) * W_DIM + w0 + tx * 8];
            *(float4*)dst       = make_float4(acc[i][0], acc[i][1], acc[i][2], acc[i][3]);
            *(float4*)(dst + 4) = make_float4(acc[i][4], acc[i][5], acc[i][6], acc[i][7]);
        }
    } else {
        float* Pb = g_P + (size_t)bc * F_DIM * W_DIM;
        float* Qb = g_Q + (size_t)bc * F_DIM * W_DIM;
#pragma unroll
        for (int i = 0; i < 8; i += 2) {
            const int r0 = ty * 8 + i;
            const int hd = r0 & 63;
            float q0[8], q1[8];
            if (hd < 32) {
                const int j = hd >> 1;
#pragma unroll
                for (int jc = 0; jc < 8; jc++) {
                    float2 cs = csT[(tx * 8 + jc) * 16 + j];
                    q0[jc] = acc[i][jc]     * cs.x - acc[i + 1][jc] * cs.y;
                    q1[jc] = acc[i + 1][jc] * cs.x + acc[i][jc]     * cs.y;
                }
            } else {
#pragma unroll
                for (int jc = 0; jc < 8; jc++) { q0[jc] = acc[i][jc]; q1[jc] = acc[i + 1][jc]; }
            }
            float* p0 = &Pb[(size_t)(g0 + r0) * W_DIM + w0 + tx * 8];
            float* p1 = p0 + W_DIM;
            *(float4*)p0       = make_float4(acc[i][0], acc[i][1], acc[i][2], acc[i][3]);
            *(float4*)(p0 + 4) = make_float4(acc[i][4], acc[i][5], acc[i][6], acc[i][7]);
            *(float4*)p1       = make_float4(acc[i+1][0], acc[i+1][1], acc[i+1][2], acc[i+1][3]);
            *(float4*)(p1 + 4) = make_float4(acc[i+1][4], acc[i+1][5], acc[i+1][6], acc[i+1][7]);
            float* t0 = &Qb[(size_t)(g0 + r0) * W_DIM + w0 + tx * 8];
            float* t1 = t0 + W_DIM;
            *(float4*)t0       = make_float4(q0[0], q0[1], q0[2], q0[3]);
            *(float4*)(t0 + 4) = make_float4(q0[4], q0[5], q0[6], q0[7]);
            *(float4*)t1       = make_float4(q1[0], q1[1], q1[2], q1[3]);
            *(float4*)(t1 + 4) = make_float4(q1[4], q1[5], q1[6], q1[7]);
        }
    }
}

// ---------------------------------------------------------------------------
// Flash attention, tf32 mma.sync (m16n8k8). K == Q. 128 q/CTA, 8 warps,
// each warp owns a 16-row stripe; softmax in registers; Q frags resident.
// smem: Ks[64][64 swz] (4096) | Vs[64][68] (4352) | Qstage overlaps [0,8192)
//       Ps: 8 warps x [16][68] (8704) at offset 8448.  Total 17152 f = 68608 B.
// grid (8 q-tiles, 64 head-batches), 256 threads, 2 CTA/SM.
// ---------------------------------------------------------------------------
__global__ __launch_bounds__(256, 2) void attn_kernel() {
    extern __shared__ float sm[];
    float* Ks     = sm;            // [k][64] swizzled tf32
    float* Vs     = sm + 4096;     // [d][68] tf32
    float* Qstage = sm;            // [q][64] swizzled tf32 (prologue only)
    float* Psw    = sm + 8448 + (threadIdx.x >> 5) * 1088;  // warp-private [16][68]

    const int tid  = threadIdx.x;
    const int warp = tid >> 5;
    const int lane = tid & 31;
    const int gid  = lane >> 2;    // 0..7
    const int tg   = lane & 3;     // 0..3
    const int q0   = blockIdx.x * 128;
    const int bcn  = blockIdx.y;

    const float* Qb = g_Q + (size_t)bcn * (NHD * W_DIM);
    const float* Vb = g_P + (size_t)bcn * (NHD * W_DIM);
    float*       Ab = g_A + (size_t)bcn * (NHD * W_DIM);

    // ---- stage Q: [q][d] swizzled, scaled, tf32 ----
#pragma unroll
    for (int it = 0; it < 8; it++) {
        int d  = (tid >> 5) + 8 * it;
        int q4 = 4 * (tid & 31);
        float4 v = *(const float4*)&Qb[(size_t)d * W_DIM + q0 + q4];
        Qstage[(q4 + 0) * 64 + SWZ(d, q4 + 0)] = f2tf(v.x * QK_SCALE);
        Qstage[(q4 + 1) * 64 + SWZ(d, q4 + 1)] = f2tf(v.y * QK_SCALE);
        Qstage[(q4 + 2) * 64 + SWZ(d, q4 + 2)] = f2tf(v.z * QK_SCALE);
        Qstage[(q4 + 3) * 64 + SWZ(d, q4 + 3)] = f2tf(v.w * QK_SCALE);
    }
    __syncthreads();

    // ---- Q fragments resident in registers: 8 k-chunks x 4 regs ----
    unsigned qa[8][4];
    {
        const int r0 = warp * 16 + gid;
        const int r1 = r0 + 8;
#pragma unroll
        for (int c = 0; c < 8; c++) {
            int d = 8 * c + tg;
            qa[c][0] = __float_as_uint(Qstage[r0 * 64 + SWZ(d, r0)]);
            qa[c][1] = __float_as_uint(Qstage[r1 * 64 + SWZ(d, r1)]);
            qa[c][2] = __float_as_uint(Qstage[r0 * 64 + SWZ(d + 4, r0)]);
            qa[c][3] = __float_as_uint(Qstage[r1 * 64 + SWZ(d + 4, r1)]);
        }
    }

    float o[8][4];
#pragma unroll
    for (int nt = 0; nt < 8; nt++)
#pragma unroll
        for (int j = 0; j < 4; j++) o[nt][j] = 0.f;
    float m0 = -1e30f, m1 = -1e30f, l0 = 0.f, l1 = 0.f;

    for (int kt = 0; kt < 16; kt++) {
        const int k0 = kt * 64;
        __syncthreads();   // also covers Qstage->Ks/Vs reuse on kt==0
        // K: transpose to [k][d] swizzled; V: direct [d][68]; both tf32
#pragma unroll
        for (int it = 0; it < 4; it++) {
            int d  = (tid >> 4) + 16 * it;
            int k4 = 4 * (tid & 15);
            float4 kv = *(const float4*)&Qb[(size_t)d * W_DIM + k0 + k4];
            Ks[(k4 + 0) * 64 + SWZ(d, k4 + 0)] = f2tf(kv.x);
            Ks[(k4 + 1) * 64 + SWZ(d, k4 + 1)] = f2tf(kv.y);
            Ks[(k4 + 2) * 64 + SWZ(d, k4 + 2)] = f2tf(kv.z);
            Ks[(k4 + 3) * 64 + SWZ(d, k4 + 3)] = f2tf(kv.w);
            float4 vv = *(const float4*)&Vb[(size_t)d * W_DIM + k0 + k4];
            *(float4*)&Vs[d * 68 + k4] =
                make_float4(f2tf(vv.x), f2tf(vv.y), f2tf(vv.z), f2tf(vv.w));
        }
        __syncthreads();

        // ---- S = Q K^T : warp stripe 16 x 64 ----
        float s[8][4];
#pragma unroll
        for (int nt = 0; nt < 8; nt++)
#pragma unroll
            for (int j = 0; j < 4; j++) s[nt][j] = 0.f;
#pragma unroll
        for (int c = 0; c < 8; c++) {
            const int d = 8 * c + tg;
#pragma unroll
            for (int nt = 0; nt < 8; nt++) {
                const int kk = nt * 8 + gid;
                unsigned b0 = __float_as_uint(Ks[kk * 64 + SWZ(d, kk)]);
                unsigned b1 = __float_as_uint(Ks[kk * 64 + SWZ(d + 4, kk)]);
                mma_tf32(s[nt], qa[c][0], qa[c][1], qa[c][2], qa[c][3], b0, b1);
            }
        }

        // ---- online softmax in registers (rows gid, gid+8) ----
        float mx0 = -1e30f, mx1 = -1e30f;
#pragma unroll
        for (int nt = 0; nt < 8; nt++) {
            mx0 = fmaxf(mx0, fmaxf(s[nt][0], s[nt][1]));
            mx1 = fmaxf(mx1, fmaxf(s[nt][2], s[nt][3]));
        }
        mx0 = fmaxf(mx0, __shfl_xor_sync(0xffffffffu, mx0, 1));
        mx0 = fmaxf(mx0, __shfl_xor_sync(0xffffffffu, mx0, 2));
        mx1 = fmaxf(mx1, __shfl_xor_sync(0xffffffffu, mx1, 1));
        mx1 = fmaxf(mx1, __shfl_xor_sync(0xffffffffu, mx1, 2));
        float mn0 = fmaxf(m0, mx0), mn1 = fmaxf(m1, mx1);
        float al0 = __expf(m0 - mn0), al1 = __expf(m1 - mn1);
        m0 = mn0; m1 = mn1;

        float ps0 = 0.f, ps1 = 0.f;
#pragma unroll
        for (int nt = 0; nt < 8; nt++) {
            float p00 = __expf(s[nt][0] - mn0);
            float p01 = __expf(s[nt][1] - mn0);
            float p10 = __expf(s[nt][2] - mn1);
            float p11 = __expf(s[nt][3] - mn1);
            ps0 += p00 + p01; ps1 += p10 + p11;
            *(float2*)&Psw[gid * 68 + nt * 8 + 2 * tg] =
                make_float2(f2tf(p00), f2tf(p01));
            *(float2*)&Psw[(gid + 8) * 68 + nt * 8 + 2 * tg] =
                make_float2(f2tf(p10), f2tf(p11));
        }
        l0 = l0 * al0 + ps0;
        l1 = l1 * al1 + ps1;
#pragma unroll
        for (int nt = 0; nt < 8; nt++) {
            o[nt][0] *= al0; o[nt][1] *= al0; o[nt][2] *= al1; o[nt][3] *= al1;
        }
        __syncwarp();

        // ---- O += P V ----
#pragma unroll
        for (int c = 0; c < 8; c++) {
            const int kk = 8 * c + tg;
            unsigned pa0 = __float_as_uint(Psw[gid * 68 + kk]);
            unsigned pa1 = __float_as_uint(Psw[(gid + 8) * 68 + kk]);
            unsigned pa2 = __float_as_uint(Psw[gid * 68 + kk + 4]);
            unsigned pa3 = __float_as_uint(Psw[(gid + 8) * 68 + kk + 4]);
#pragma unroll
            for (int nt = 0; nt < 8; nt++) {
                const int d = nt * 8 + gid;
                unsigned b0 = __float_as_uint(Vs[d * 68 + kk]);
                unsigned b1 = __float_as_uint(Vs[d * 68 + kk + 4]);
                mma_tf32(o[nt], pa0, pa1, pa2, pa3, b0, b1);
            }
        }
        __syncwarp();   // Psw rewritten next tile
    }

    // ---- epilogue ----
    l0 += __shfl_xor_sync(0xffffffffu, l0, 1);
    l0 += __shfl_xor_sync(0xffffffffu, l0, 2);
    l1 += __shfl_xor_sync(0xffffffffu, l1, 1);
    l1 += __shfl_xor_sync(0xffffffffu, l1, 2);
    float inv0 = 1.f / l0, inv1 = 1.f / l1;
#pragma unroll
    for (int nt = 0; nt < 8; nt++) {
        *(float2*)&Psw[gid * 68 + nt * 8 + 2 * tg] =
            make_float2(o[nt][0] * inv0, o[nt][1] * inv0);
        *(float2*)&Psw[(gid + 8) * 68 + nt * 8 + 2 * tg] =
            make_float2(o[nt][2] * inv1, o[nt][3] * inv1);
    }
    __syncwarp();
#pragma unroll
    for (int i = 0; i < 32; i++) {
        int idx = 32 * i + lane;
        int d = idx >> 4, qf = idx & 15;
        Ab[(size_t)d * W_DIM + q0 + warp * 16 + qf] = Psw[qf * 68 + d];
    }
}

// ---------------------------------------------------------------------------
// Launch. Inputs: x, wq, wk, wv, wo, freqs_param (wk/wv dead in reference).
// ---------------------------------------------------------------------------
extern "C" void kernel_launch(void* const* d_in, const int* in_sizes, int n_in,
                              void* d_out, int out_size) {
    (void)in_sizes; (void)n_in; (void)out_size;
    const float* x  = (const float*)d_in[0];
    const float* wq = (const float*)d_in[1];
    const float* wo = (const float*)d_in[4];
    const float* fp = (const float*)d_in[5];
    float* out = (float*)d_out;

    cudaFuncSetAttribute(gemm_kernel, cudaFuncAttributeMaxDynamicSharedMemorySize, 53248);
    cudaFuncSetAttribute(attn_kernel, cudaFuncAttributeMaxDynamicSharedMemorySize, 68608);

    dim3 gg(8, 4, 8);
    gemm_kernel<<<gg, 256, 53248>>>(wq, x, nullptr, fp, 0);        // P + roped Q
    attn_kernel<<<dim3(8, 64), 256, 68608>>>();                    // tf32 mma flash attn
    gemm_kernel<<<gg, 256, 36864>>>(wo, nullptr, out, nullptr, 1); // out = Wo @ A
}

// round 4
// speedup vs baseline: 3.2934x; 1.4240x over previous
#include <cuda_runtime.h>

#define W_DIM 1024
#define F_DIM 512
#define NHD   64
#define NBC   8
#define BCSTRIDE 524288   // 512*1024
#define QK_SCALE 0.044194173824159216f  // 1/sqrt(512)

__device__ float g_P[NBC * F_DIM * W_DIM];   // projection (V source), [bc][g][w] fp32
__device__ float g_Q[NBC * F_DIM * W_DIM];   // roped Q == roped K,    [bc][g][w] fp32
__device__ float g_A[NBC * F_DIM * W_DIM];   // attn out TRANSPOSED    [bc][w][h] tf32
__device__ float g_XT[NBC * F_DIM * W_DIM];  // x transposed           [bc][w][h] tf32
__device__ float g_Wq[2 * F_DIM * F_DIM];    // tf32 wq
__device__ float g_Wo[2 * F_DIM * F_DIM];    // tf32 wo

// ---------------------------------------------------------------------------
// helpers
// ---------------------------------------------------------------------------
__device__ __forceinline__ void cp_async16(void* smem_dst, const void* gsrc) {
    unsigned sdst = (unsigned)__cvta_generic_to_shared(smem_dst);
    asm volatile("cp.async.ca.shared.global [%0], [%1], 16;\n" :: "r"(sdst), "l"(gsrc));
}
#define CP_COMMIT() asm volatile("cp.async.commit_group;\n" ::)
#define CP_WAIT1()  asm volatile("cp.async.wait_group 1;\n" ::)
#define CP_WAIT0()  asm volatile("cp.async.wait_group 0;\n" ::)

__device__ __forceinline__ float f2tf(float f) {
    unsigned r;
    asm("cvt.rna.tf32.f32 %0, %1;" : "=r"(r) : "f"(f));
    return __uint_as_float(r);
}
__device__ __forceinline__ void mma_tf32(float c[4], unsigned a0, unsigned a1,
                                         unsigned a2, unsigned a3,
                                         unsigned b0, unsigned b1) {
    asm volatile("mma.sync.aligned.m16n8k8.row.col.f32.tf32.tf32.f32 "
                 "{%0,%1,%2,%3},{%4,%5,%6,%7},{%8,%9},{%0,%1,%2,%3};"
                 : "+f"(c[0]), "+f"(c[1]), "+f"(c[2]), "+f"(c[3])
                 : "r"(a0), "r"(a1), "r"(a2), "r"(a3), "r"(b0), "r"(b1));
}
#define SWZ(d, t) ((((((d) >> 2) ^ ((t) & 15)) << 2)) | ((d) & 3))

// ---------------------------------------------------------------------------
// prep: round weights to tf32
// ---------------------------------------------------------------------------
__global__ void prepw_kernel(const float* __restrict__ wq, const float* __restrict__ wo) {
    int i = blockIdx.x * 256 + threadIdx.x;   // 524288 total
    g_Wq[i] = f2tf(wq[i]);
    g_Wo[i] = f2tf(wo[i]);
}

// ---------------------------------------------------------------------------
// transpose x[bc][h][w] -> g_XT[bc][w][h], tf32-rounded
// ---------------------------------------------------------------------------
__global__ void transpose_kernel(const float* __restrict__ x) {
    __shared__ float t[32][33];
    const int bc = blockIdx.z;
    const int w0 = blockIdx.x * 32, h0 = blockIdx.y * 32;
    const int tx = threadIdx.x, ty = threadIdx.y;
    const float* xb = x + (size_t)bc * BCSTRIDE;
#pragma unroll
    for (int i = 0; i < 4; i++)
        t[ty + 8 * i][tx] = xb[(size_t)(h0 + ty + 8 * i) * W_DIM + w0 + tx];
    __syncthreads();
    float* xt = g_XT + (size_t)bc * BCSTRIDE;
#pragma unroll
    for (int i = 0; i < 4; i++)
        xt[(size_t)(w0 + ty + 8 * i) * F_DIM + h0 + tx] = f2tf(t[tx][ty + 8 * i]);
}

// ---------------------------------------------------------------------------
// tf32 tensor-core GEMM: Out[g][w] = sum_h W[g][h] * X[w][h]  (X pre-transposed)
// 128x128 tile, BK=16 double-buffered cp.async, 8 warps (4m x 2n),
// warp computes 32(m) x 64(n). mode 0: A=g_Wq, B=g_XT, epilogue writes
// g_P (raw) + g_Q (RoPE fused). mode 1: A=g_Wo, B=g_A, writes Op.
// ---------------------------------------------------------------------------
__global__ __launch_bounds__(256, 2) void gemm_tc(float* __restrict__ Op,
                                                  const float* __restrict__ fp,
                                                  int mode) {
    extern __shared__ float sm[];
    float*  As  = sm;                       // 2 * 128*20
    float*  Bs  = sm + 5120;                // 2 * 128*20
    float2* csT = (float2*)(sm + 10240);    // 2048 float2 (mode 0 only)

    const int bc = blockIdx.z;
    const float* Wb = (mode == 0 ? g_Wq : g_Wo) + (size_t)(bc & 1) * (F_DIM * F_DIM);
    const float* Xb = (mode == 0 ? g_XT : g_A) + (size_t)bc * BCSTRIDE;

    const int g0 = blockIdx.y * 128;
    const int w0 = blockIdx.x * 128;
    const int tid = threadIdx.x;
    const int warp = tid >> 5, lane = tid & 31;
    const int wm = warp >> 1, wn = warp & 1;
    const int gid = lane >> 2, tg = lane & 3;
    const int lg = tid >> 2, lw = tid & 3;

    // prologue loads (tile 0)
    cp_async16(&As[lg * 20 + lw * 4],        &Wb[(size_t)(g0 + lg) * F_DIM + lw * 4]);
    cp_async16(&As[(lg + 64) * 20 + lw * 4], &Wb[(size_t)(g0 + lg + 64) * F_DIM + lw * 4]);
    cp_async16(&Bs[lg * 20 + lw * 4],        &Xb[(size_t)(w0 + lg) * F_DIM + lw * 4]);
    cp_async16(&Bs[(lg + 64) * 20 + lw * 4], &Xb[(size_t)(w0 + lg + 64) * F_DIM + lw * 4]);
    CP_COMMIT();

    if (mode == 0) {
        for (int t = tid; t < 2048; t += 256) {
            int wl = t >> 4, j = t & 15;
            float sv, cv;
            sincosf((float)(w0 + wl) * fp[j], &sv, &cv);
            csT[t] = make_float2(cv, sv);
        }
    }

    float acc[2][8][4];
#pragma unroll
    for (int mf = 0; mf < 2; mf++)
#pragma unroll
        for (int nt = 0; nt < 8; nt++)
#pragma unroll
            for (int j = 0; j < 4; j++) acc[mf][nt][j] = 0.f;

    for (int t = 0; t < 32; t++) {
        const int buf = t & 1;
        if (t < 31) {
            const int k0 = (t + 1) * 16;
            float* An = As + (buf ^ 1) * 2560;
            float* Bn = Bs + (buf ^ 1) * 2560;
            cp_async16(&An[lg * 20 + lw * 4],        &Wb[(size_t)(g0 + lg) * F_DIM + k0 + lw * 4]);
            cp_async16(&An[(lg + 64) * 20 + lw * 4], &Wb[(size_t)(g0 + lg + 64) * F_DIM + k0 + lw * 4]);
            cp_async16(&Bn[lg * 20 + lw * 4],        &Xb[(size_t)(w0 + lg) * F_DIM + k0 + lw * 4]);
            cp_async16(&Bn[(lg + 64) * 20 + lw * 4], &Xb[(size_t)(w0 + lg + 64) * F_DIM + k0 + lw * 4]);
            CP_COMMIT();
            CP_WAIT1();
        } else {
            CP_WAIT0();
        }
        __syncthreads();
        const float* Ab = As + buf * 2560;
        const float* Bb = Bs + buf * 2560;
#pragma unroll
        for (int cb = 0; cb < 16; cb += 8) {
            unsigned a[2][4];
#pragma unroll
            for (int mf = 0; mf < 2; mf++) {
                const int m = wm * 32 + mf * 16 + gid;
                a[mf][0] = __float_as_uint(Ab[m * 20 + cb + tg]);
                a[mf][1] = __float_as_uint(Ab[(m + 8) * 20 + cb + tg]);
                a[mf][2] = __float_as_uint(Ab[m * 20 + cb + tg + 4]);
                a[mf][3] = __float_as_uint(Ab[(m + 8) * 20 + cb + tg + 4]);
            }
#pragma unroll
            for (int nt = 0; nt < 8; nt++) {
                const int n = wn * 64 + nt * 8 + gid;
                unsigned b0 = __float_as_uint(Bb[n * 20 + cb + tg]);
                unsigned b1 = __float_as_uint(Bb[n * 20 + cb + tg + 4]);
                mma_tf32(acc[0][nt], a[0][0], a[0][1], a[0][2], a[0][3], b0, b1);
                mma_tf32(acc[1][nt], a[1][0], a[1][1], a[1][2], a[1][3], b0, b1);
            }
        }
        __syncthreads();
    }

    if (mode == 1) {
#pragma unroll
        for (int mf = 0; mf < 2; mf++) {
            const int rA = wm * 32 + mf * 16 + gid;
            const int rB = rA + 8;
#pragma unroll
            for (int nt = 0; nt < 8; nt++) {
                const int col = w0 + wn * 64 + nt * 8 + 2 * tg;
                float* dA = &Op[(size_t)bc * BCSTRIDE + (size_t)(g0 + rA) * W_DIM + col];
                float* dB = &Op[(size_t)bc * BCSTRIDE + (size_t)(g0 + rB) * W_DIM + col];
                *(float2*)dA = make_float2(acc[mf][nt][0], acc[mf][nt][1]);
                *(float2*)dB = make_float2(acc[mf][nt][2], acc[mf][nt][3]);
            }
        }
    } else {
        // fused RoPE epilogue; pair partner row (r^1) sits at lane^4
        float* Pb = g_P + (size_t)bc * BCSTRIDE;
        float* Qb = g_Q + (size_t)bc * BCSTRIDE;
#pragma unroll
        for (int mf = 0; mf < 2; mf++) {
            const int rA = wm * 32 + mf * 16 + gid;
            const int rB = rA + 8;
            const int hdA = rA & 63, hdB = rB & 63;
            const float sgn = (gid & 1) ? 1.f : -1.f;   // even row: -sin, odd: +sin
#pragma unroll
            for (int nt = 0; nt < 8; nt++) {
                float c0 = acc[mf][nt][0], c1 = acc[mf][nt][1];
                float c2 = acc[mf][nt][2], c3 = acc[mf][nt][3];
                float p0 = __shfl_xor_sync(0xffffffffu, c0, 4);
                float p1 = __shfl_xor_sync(0xffffffffu, c1, 4);
                float p2 = __shfl_xor_sync(0xffffffffu, c2, 4);
                float p3 = __shfl_xor_sync(0xffffffffu, c3, 4);
                const int cl = wn * 64 + nt * 8 + 2 * tg;
                float qa0 = c0, qa1 = c1, qb0 = c2, qb1 = c3;
                if (hdA < 32) {
                    const int j = hdA >> 1;
                    float2 cs0 = csT[cl * 16 + j];
                    float2 cs1 = csT[(cl + 1) * 16 + j];
                    qa0 = c0 * cs0.x + sgn * p0 * cs0.y;
                    qa1 = c1 * cs1.x + sgn * p1 * cs1.y;
                }
                if (hdB < 32) {
                    const int j = hdB >> 1;
                    float2 cs0 = csT[cl * 16 + j];
                    float2 cs1 = csT[(cl + 1) * 16 + j];
                    qb0 = c2 * cs0.x + sgn * p2 * cs0.y;
                    qb1 = c3 * cs1.x + sgn * p3 * cs1.y;
                }
                const int col = w0 + cl;
                *(float2*)&Pb[(size_t)(g0 + rA) * W_DIM + col] = make_float2(c0, c1);
                *(float2*)&Pb[(size_t)(g0 + rB) * W_DIM + col] = make_float2(c2, c3);
                *(float2*)&Qb[(size_t)(g0 + rA) * W_DIM + col] = make_float2(qa0, qa1);
                *(float2*)&Qb[(size_t)(g0 + rB) * W_DIM + col] = make_float2(qb0, qb1);
            }
        }
    }
}

// ---------------------------------------------------------------------------
// Flash attention, tf32 mma.sync. K == Q. Identical to R3 except the epilogue
// writes g_A TRANSPOSED [bc][w][h] and tf32-rounded (feeds gemm_tc mode 1).
// ---------------------------------------------------------------------------
__global__ __launch_bounds__(256, 2) void attn_kernel() {
    extern __shared__ float sm[];
    float* Ks     = sm;            // [k][64] swizzled tf32
    float* Vs     = sm + 4096;     // [d][68] tf32
    float* Qstage = sm;            // [q][64] swizzled tf32 (prologue only)
    float* Psw    = sm + 8448 + (threadIdx.x >> 5) * 1088;  // warp-private [16][68]

    const int tid  = threadIdx.x;
    const int warp = tid >> 5;
    const int lane = tid & 31;
    const int gid  = lane >> 2;
    const int tg   = lane & 3;
    const int q0   = blockIdx.x * 128;
    const int bcn  = blockIdx.y;

    const float* Qb = g_Q + (size_t)bcn * (NHD * W_DIM);
    const float* Vb = g_P + (size_t)bcn * (NHD * W_DIM);

#pragma unroll
    for (int it = 0; it < 8; it++) {
        int d  = (tid >> 5) + 8 * it;
        int q4 = 4 * (tid & 31);
        float4 v = *(const float4*)&Qb[(size_t)d * W_DIM + q0 + q4];
        Qstage[(q4 + 0) * 64 + SWZ(d, q4 + 0)] = f2tf(v.x * QK_SCALE);
        Qstage[(q4 + 1) * 64 + SWZ(d, q4 + 1)] = f2tf(v.y * QK_SCALE);
        Qstage[(q4 + 2) * 64 + SWZ(d, q4 + 2)] = f2tf(v.z * QK_SCALE);
        Qstage[(q4 + 3) * 64 + SWZ(d, q4 + 3)] = f2tf(v.w * QK_SCALE);
    }
    __syncthreads();

    unsigned qa[8][4];
    {
        const int r0 = warp * 16 + gid;
        const int r1 = r0 + 8;
#pragma unroll
        for (int c = 0; c < 8; c++) {
            int d = 8 * c + tg;
            qa[c][0] = __float_as_uint(Qstage[r0 * 64 + SWZ(d, r0)]);
            qa[c][1] = __float_as_uint(Qstage[r1 * 64 + SWZ(d, r1)]);
            qa[c][2] = __float_as_uint(Qstage[r0 * 64 + SWZ(d + 4, r0)]);
            qa[c][3] = __float_as_uint(Qstage[r1 * 64 + SWZ(d + 4, r1)]);
        }
    }

    float o[8][4];
#pragma unroll
    for (int nt = 0; nt < 8; nt++)
#pragma unroll
        for (int j = 0; j < 4; j++) o[nt][j] = 0.f;
    float m0 = -1e30f, m1 = -1e30f, l0 = 0.f, l1 = 0.f;

    for (int kt = 0; kt < 16; kt++) {
        const int k0 = kt * 64;
        __syncthreads();
#pragma unroll
        for (int it = 0; it < 4; it++) {
            int d  = (tid >> 4) + 16 * it;
            int k4 = 4 * (tid & 15);
            float4 kv = *(const float4*)&Qb[(size_t)d * W_DIM + k0 + k4];
            Ks[(k4 + 0) * 64 + SWZ(d, k4 + 0)] = f2tf(kv.x);
            Ks[(k4 + 1) * 64 + SWZ(d, k4 + 1)] = f2tf(kv.y);
            Ks[(k4 + 2) * 64 + SWZ(d, k4 + 2)] = f2tf(kv.z);
            Ks[(k4 + 3) * 64 + SWZ(d, k4 + 3)] = f2tf(kv.w);
            float4 vv = *(const float4*)&Vb[(size_t)d * W_DIM + k0 + k4];
            *(float4*)&Vs[d * 68 + k4] =
                make_float4(f2tf(vv.x), f2tf(vv.y), f2tf(vv.z), f2tf(vv.w));
        }
        __syncthreads();

        float s[8][4];
#pragma unroll
        for (int nt = 0; nt < 8; nt++)
#pragma unroll
            for (int j = 0; j < 4; j++) s[nt][j] = 0.f;
#pragma unroll
        for (int c = 0; c < 8; c++) {
            const int d = 8 * c + tg;
#pragma unroll
            for (int nt = 0; nt < 8; nt++) {
                const int kk = nt * 8 + gid;
                unsigned b0 = __float_as_uint(Ks[kk * 64 + SWZ(d, kk)]);
                unsigned b1 = __float_as_uint(Ks[kk * 64 + SWZ(d + 4, kk)]);
                mma_tf32(s[nt], qa[c][0], qa[c][1], qa[c][2], qa[c][3], b0, b1);
            }
        }

        float mx0 = -1e30f, mx1 = -1e30f;
#pragma unroll
        for (int nt = 0; nt < 8; nt++) {
            mx0 = fmaxf(mx0, fmaxf(s[nt][0], s[nt][1]));
            mx1 = fmaxf(mx1, fmaxf(s[nt][2], s[nt][3]));
        }
        mx0 = fmaxf(mx0, __shfl_xor_sync(0xffffffffu, mx0, 1));
        mx0 = fmaxf(mx0, __shfl_xor_sync(0xffffffffu, mx0, 2));
        mx1 = fmaxf(mx1, __shfl_xor_sync(0xffffffffu, mx1, 1));
        mx1 = fmaxf(mx1, __shfl_xor_sync(0xffffffffu, mx1, 2));
        float mn0 = fmaxf(m0, mx0), mn1 = fmaxf(m1, mx1);
        float al0 = __expf(m0 - mn0), al1 = __expf(m1 - mn1);
        m0 = mn0; m1 = mn1;

        float ps0 = 0.f, ps1 = 0.f;
#pragma unroll
        for (int nt = 0; nt < 8; nt++) {
            float p00 = __expf(s[nt][0] - mn0);
            float p01 = __expf(s[nt][1] - mn0);
            float p10 = __expf(s[nt][2] - mn1);
            float p11 = __expf(s[nt][3] - mn1);
            ps0 += p00 + p01; ps1 += p10 + p11;
            *(float2*)&Psw[gid * 68 + nt * 8 + 2 * tg] =
                make_float2(f2tf(p00), f2tf(p01));
            *(float2*)&Psw[(gid + 8) * 68 + nt * 8 + 2 * tg] =
                make_float2(f2tf(p10), f2tf(p11));
        }
        l0 = l0 * al0 + ps0;
        l1 = l1 * al1 + ps1;
#pragma unroll
        for (int nt = 0; nt < 8; nt++) {
            o[nt][0] *= al0; o[nt][1] *= al0; o[nt][2] *= al1; o[nt][3] *= al1;
        }
        __syncwarp();

#pragma unroll
        for (int c = 0; c < 8; c++) {
            const int kk = 8 * c + tg;
            unsigned pa0 = __float_as_uint(Psw[gid * 68 + kk]);
            unsigned pa1 = __float_as_uint(Psw[(gid + 8) * 68 + kk]);
            unsigned pa2 = __float_as_uint(Psw[gid * 68 + kk + 4]);
            unsigned pa3 = __float_as_uint(Psw[(gid + 8) * 68 + kk + 4]);
#pragma unroll
            for (int nt = 0; nt < 8; nt++) {
                const int d = nt * 8 + gid;
                unsigned b0 = __float_as_uint(Vs[d * 68 + kk]);
                unsigned b1 = __float_as_uint(Vs[d * 68 + kk + 4]);
                mma_tf32(o[nt], pa0, pa1, pa2, pa3, b0, b1);
            }
        }
        __syncwarp();
    }

    // epilogue: normalize, stage [q][d], write transposed tf32 to g_A[bc][w][h]
    l0 += __shfl_xor_sync(0xffffffffu, l0, 1);
    l0 += __shfl_xor_sync(0xffffffffu, l0, 2);
    l1 += __shfl_xor_sync(0xffffffffu, l1, 1);
    l1 += __shfl_xor_sync(0xffffffffu, l1, 2);
    float inv0 = 1.f / l0, inv1 = 1.f / l1;
#pragma unroll
    for (int nt = 0; nt < 8; nt++) {
        *(float2*)&Psw[gid * 68 + nt * 8 + 2 * tg] =
            make_float2(o[nt][0] * inv0, o[nt][1] * inv0);
        *(float2*)&Psw[(gid + 8) * 68 + nt * 8 + 2 * tg] =
            make_float2(o[nt][2] * inv1, o[nt][3] * inv1);
    }
    __syncwarp();
    const int bc = bcn >> 3, nh = bcn & 7;
    float* Ab2 = g_A + (size_t)bc * BCSTRIDE + nh * 64;
#pragma unroll
    for (int i = 0; i < 16; i++) {
        float2 v = *(float2*)&Psw[i * 68 + 2 * lane];
        v.x = f2tf(v.x); v.y = f2tf(v.y);
        *(float2*)&Ab2[(size_t)(q0 + warp * 16 + i) * F_DIM + 2 * lane] = v;
    }
}

// ---------------------------------------------------------------------------
// Launch. Inputs: x, wq, wk, wv, wo, freqs_param (wk/wv dead in reference).
// ---------------------------------------------------------------------------
extern "C" void kernel_launch(void* const* d_in, const int* in_sizes, int n_in,
                              void* d_out, int out_size) {
    (void)in_sizes; (void)n_in; (void)out_size;
    const float* x  = (const float*)d_in[0];
    const float* wq = (const float*)d_in[1];
    const float* wo = (const float*)d_in[4];
    const float* fp = (const float*)d_in[5];
    float* out = (float*)d_out;

    cudaFuncSetAttribute(gemm_tc,    cudaFuncAttributeMaxDynamicSharedMemorySize, 57344);
    cudaFuncSetAttribute(attn_kernel, cudaFuncAttributeMaxDynamicSharedMemorySize, 68608);

    prepw_kernel<<<2048, 256>>>(wq, wo);
    transpose_kernel<<<dim3(32, 16, 8), dim3(32, 8)>>>(x);

    dim3 gg(8, 4, 8);
    gemm_tc<<<gg, 256, 57344>>>(nullptr, fp, 0);     // g_P + roped g_Q
    attn_kernel<<<dim3(8, 64), 256, 68608>>>();      // g_A (transposed, tf32)
    gemm_tc<<<gg, 256, 40960>>>(out, nullptr, 1);    // out = Wo @ A
}

// round 6
// speedup vs baseline: 4.3558x; 1.3226x over previous
#include <cuda_runtime.h>

#define W_DIM 1024
#define F_DIM 512
#define NBC   8
#define BCSTRIDE 524288   // 512*1024
#define QK_SCALE 0.044194173824159216f      // 1/sqrt(512)
#define SCL2     0.06375871886660017f       // QK_SCALE * log2(e)

__device__ float g_P [NBC * F_DIM * W_DIM];  // projection tf32, [bc][g][w] (V source)
__device__ float g_QT[NBC * F_DIM * W_DIM];  // roped Q==K, TRANSPOSED tf32 [bc][w][h]
__device__ float g_A [NBC * F_DIM * W_DIM];  // attn out TRANSPOSED tf32 [bc][w][h]
__device__ float g_XT[NBC * F_DIM * W_DIM];  // x transposed tf32 [bc][w][h]
__device__ float g_Wq[2 * F_DIM * F_DIM];    // tf32 wq
__device__ float g_Wo[2 * F_DIM * F_DIM];    // tf32 wo

// ---------------------------------------------------------------------------
// helpers
// ---------------------------------------------------------------------------
__device__ __forceinline__ void cp_async16(void* smem_dst, const void* gsrc) {
    unsigned sdst = (unsigned)__cvta_generic_to_shared(smem_dst);
    asm volatile("cp.async.ca.shared.global [%0], [%1], 16;\n" :: "r"(sdst), "l"(gsrc));
}
#define CP_COMMIT() asm volatile("cp.async.commit_group;\n" ::)
#define CP_WAIT1()  asm volatile("cp.async.wait_group 1;\n" ::)
#define CP_WAIT0()  asm volatile("cp.async.wait_group 0;\n" ::)

__device__ __forceinline__ float f2tf(float f) {
    unsigned r;
    asm("cvt.rna.tf32.f32 %0, %1;" : "=r"(r) : "f"(f));
    return __uint_as_float(r);
}
__device__ __forceinline__ void mma_tf32(float c[4], unsigned a0, unsigned a1,
                                         unsigned a2, unsigned a3,
                                         unsigned b0, unsigned b1) {
    asm volatile("mma.sync.aligned.m16n8k8.row.col.f32.tf32.tf32.f32 "
                 "{%0,%1,%2,%3},{%4,%5,%6,%7},{%8,%9},{%0,%1,%2,%3};"
                 : "+f"(c[0]), "+f"(c[1]), "+f"(c[2]), "+f"(c[3])
                 : "r"(a0), "r"(a1), "r"(a2), "r"(a3), "r"(b0), "r"(b1));
}
__device__ __forceinline__ void ldsm4(unsigned& r0, unsigned& r1, unsigned& r2,
                                      unsigned& r3, unsigned addr) {
    asm volatile("ldmatrix.sync.aligned.m8n8.x4.shared.b16 {%0,%1,%2,%3}, [%4];"
                 : "=r"(r0), "=r"(r1), "=r"(r2), "=r"(r3) : "r"(addr));
}

// ---------------------------------------------------------------------------
// prep: round weights to tf32
// ---------------------------------------------------------------------------
__global__ void prepw_kernel(const float* __restrict__ wq, const float* __restrict__ wo) {
    int i = blockIdx.x * 256 + threadIdx.x;
    g_Wq[i] = f2tf(wq[i]);
    g_Wo[i] = f2tf(wo[i]);
}

// ---------------------------------------------------------------------------
// transpose x[bc][h][w] -> g_XT[bc][w][h], tf32-rounded
// ---------------------------------------------------------------------------
__global__ void transpose_kernel(const float* __restrict__ x) {
    __shared__ float t[32][33];
    const int bc = blockIdx.z;
    const int w0 = blockIdx.x * 32, h0 = blockIdx.y * 32;
    const int tx = threadIdx.x, ty = threadIdx.y;
    const float* xb = x + (size_t)bc * BCSTRIDE;
#pragma unroll
    for (int i = 0; i < 4; i++)
        t[ty + 8 * i][tx] = xb[(size_t)(h0 + ty + 8 * i) * W_DIM + w0 + tx];
    __syncthreads();
    float* xt = g_XT + (size_t)bc * BCSTRIDE;
#pragma unroll
    for (int i = 0; i < 4; i++)
        xt[(size_t)(w0 + ty + 8 * i) * F_DIM + h0 + tx] = f2tf(t[tx][ty + 8 * i]);
}

// ---------------------------------------------------------------------------
// tf32 tensor-core GEMM (same mainloop as R4, passing).
// mode 0: A=g_Wq, B=g_XT -> g_P (tf32) + g_QT (roped, transposed, tf32)
// mode 1: A=g_Wo, B=g_A  -> Op
// ---------------------------------------------------------------------------
__global__ __launch_bounds__(256, 2) void gemm_tc(float* __restrict__ Op,
                                                  const float* __restrict__ fp,
                                                  int mode) {
    extern __shared__ float sm[];
    float*  As  = sm;
    float*  Bs  = sm + 5120;
    float2* csT = (float2*)(sm + 10240);

    const int bc = blockIdx.z;
    const float* Wb = (mode == 0 ? g_Wq : g_Wo) + (size_t)(bc & 1) * (F_DIM * F_DIM);
    const float* Xb = (mode == 0 ? g_XT : g_A) + (size_t)bc * BCSTRIDE;

    const int g0 = blockIdx.y * 128;
    const int w0 = blockIdx.x * 128;
    const int tid = threadIdx.x;
    const int warp = tid >> 5, lane = tid & 31;
    const int wm = warp >> 1, wn = warp & 1;
    const int gid = lane >> 2, tg = lane & 3;
    const int lg = tid >> 2, lw = tid & 3;

    cp_async16(&As[lg * 20 + lw * 4],        &Wb[(size_t)(g0 + lg) * F_DIM + lw * 4]);
    cp_async16(&As[(lg + 64) * 20 + lw * 4], &Wb[(size_t)(g0 + lg + 64) * F_DIM + lw * 4]);
    cp_async16(&Bs[lg * 20 + lw * 4],        &Xb[(size_t)(w0 + lg) * F_DIM + lw * 4]);
    cp_async16(&Bs[(lg + 64) * 20 + lw * 4], &Xb[(size_t)(w0 + lg + 64) * F_DIM + lw * 4]);
    CP_COMMIT();

    if (mode == 0) {
        for (int t = tid; t < 2048; t += 256) {
            int wl = t >> 4, j = t & 15;
            float sv, cv;
            sincosf((float)(w0 + wl) * fp[j], &sv, &cv);
            csT[t] = make_float2(cv, sv);
        }
    }

    float acc[2][8][4];
#pragma unroll
    for (int mf = 0; mf < 2; mf++)
#pragma unroll
        for (int nt = 0; nt < 8; nt++)
#pragma unroll
            for (int j = 0; j < 4; j++) acc[mf][nt][j] = 0.f;

    for (int t = 0; t < 32; t++) {
        const int buf = t & 1;
        if (t < 31) {
            const int k0 = (t + 1) * 16;
            float* An = As + (buf ^ 1) * 2560;
            float* Bn = Bs + (buf ^ 1) * 2560;
            cp_async16(&An[lg * 20 + lw * 4],        &Wb[(size_t)(g0 + lg) * F_DIM + k0 + lw * 4]);
            cp_async16(&An[(lg + 64) * 20 + lw * 4], &Wb[(size_t)(g0 + lg + 64) * F_DIM + k0 + lw * 4]);
            cp_async16(&Bn[lg * 20 + lw * 4],        &Xb[(size_t)(w0 + lg) * F_DIM + k0 + lw * 4]);
            cp_async16(&Bn[(lg + 64) * 20 + lw * 4], &Xb[(size_t)(w0 + lg + 64) * F_DIM + k0 + lw * 4]);
            CP_COMMIT();
            CP_WAIT1();
        } else {
            CP_WAIT0();
        }
        __syncthreads();
        const float* Ab = As + buf * 2560;
        const float* Bb = Bs + buf * 2560;
#pragma unroll
        for (int cb = 0; cb < 16; cb += 8) {
            unsigned a[2][4];
#pragma unroll
            for (int mf = 0; mf < 2; mf++) {
                const int m = wm * 32 + mf * 16 + gid;
                a[mf][0] = __float_as_uint(Ab[m * 20 + cb + tg]);
                a[mf][1] = __float_as_uint(Ab[(m + 8) * 20 + cb + tg]);
                a[mf][2] = __float_as_uint(Ab[m * 20 + cb + tg + 4]);
                a[mf][3] = __float_as_uint(Ab[(m + 8) * 20 + cb + tg + 4]);
            }
#pragma unroll
            for (int nt = 0; nt < 8; nt++) {
                const int n = wn * 64 + nt * 8 + gid;
                unsigned b0 = __float_as_uint(Bb[n * 20 + cb + tg]);
                unsigned b1 = __float_as_uint(Bb[n * 20 + cb + tg + 4]);
                mma_tf32(acc[0][nt], a[0][0], a[0][1], a[0][2], a[0][3], b0, b1);
                mma_tf32(acc[1][nt], a[1][0], a[1][1], a[1][2], a[1][3], b0, b1);
            }
        }
        __syncthreads();
    }

    if (mode == 1) {
#pragma unroll
        for (int mf = 0; mf < 2; mf++) {
            const int rA = wm * 32 + mf * 16 + gid;
            const int rB = rA + 8;
#pragma unroll
            for (int nt = 0; nt < 8; nt++) {
                const int col = w0 + wn * 64 + nt * 8 + 2 * tg;
                float* dA = &Op[(size_t)bc * BCSTRIDE + (size_t)(g0 + rA) * W_DIM + col];
                float* dB = &Op[(size_t)bc * BCSTRIDE + (size_t)(g0 + rB) * W_DIM + col];
                *(float2*)dA = make_float2(acc[mf][nt][0], acc[mf][nt][1]);
                *(float2*)dB = make_float2(acc[mf][nt][2], acc[mf][nt][3]);
            }
        }
    } else {
        // fused RoPE epilogue; pair partner row (r^1) sits at lane^4
        float* Pb  = g_P  + (size_t)bc * BCSTRIDE;
        float* QTb = g_QT + (size_t)bc * BCSTRIDE;
#pragma unroll
        for (int mf = 0; mf < 2; mf++) {
            const int rA = wm * 32 + mf * 16 + gid;
            const int rB = rA + 8;
            const int hdA = rA & 63, hdB = rB & 63;
            const float sgn = (gid & 1) ? 1.f : -1.f;
#pragma unroll
            for (int nt = 0; nt < 8; nt++) {
                float c0 = acc[mf][nt][0], c1 = acc[mf][nt][1];
                float c2 = acc[mf][nt][2], c3 = acc[mf][nt][3];
                float p0 = __shfl_xor_sync(0xffffffffu, c0, 4);
                float p1 = __shfl_xor_sync(0xffffffffu, c1, 4);
                float p2 = __shfl_xor_sync(0xffffffffu, c2, 4);
                float p3 = __shfl_xor_sync(0xffffffffu, c3, 4);
                const int cl = wn * 64 + nt * 8 + 2 * tg;
                float qa0 = c0, qa1 = c1, qb0 = c2, qb1 = c3;
                if (hdA < 32) {
                    const int j = hdA >> 1;
                    float2 cs0 = csT[cl * 16 + j];
                    float2 cs1 = csT[(cl + 1) * 16 + j];
                    qa0 = c0 * cs0.x + sgn * p0 * cs0.y;
                    qa1 = c1 * cs1.x + sgn * p1 * cs1.y;
                }
                if (hdB < 32) {
                    const int j = hdB >> 1;
                    float2 cs0 = csT[cl * 16 + j];
                    float2 cs1 = csT[(cl + 1) * 16 + j];
                    qb0 = c2 * cs0.x + sgn * p2 * cs0.y;
                    qb1 = c3 * cs1.x + sgn * p3 * cs1.y;
                }
                const int col = w0 + cl;
                *(float2*)&Pb[(size_t)(g0 + rA) * W_DIM + col] = make_float2(f2tf(c0), f2tf(c1));
                *(float2*)&Pb[(size_t)(g0 + rB) * W_DIM + col] = make_float2(f2tf(c2), f2tf(c3));
                QTb[(size_t)col * F_DIM + g0 + rA]       = f2tf(qa0);
                QTb[(size_t)(col + 1) * F_DIM + g0 + rA] = f2tf(qa1);
                QTb[(size_t)col * F_DIM + g0 + rB]       = f2tf(qb0);
                QTb[(size_t)(col + 1) * F_DIM + g0 + rB] = f2tf(qb1);
            }
        }
    }
}

// ---------------------------------------------------------------------------
// Flash attention, tf32 mma + ldmatrix. K == Q (g_QT), V = g_P. 128 q/CTA,
// 8 warps x 16-row stripes, 64-key tiles, softmax in registers.
// smem floats: Qt[128][68] (overlaid by warp-private Psw after fragment load),
//              Kt[64][68], Vt[64][68]. Total 17408 f = 69632 B -> 2 CTA/SM.
// ---------------------------------------------------------------------------
__global__ __launch_bounds__(256, 2) void attn_kernel() {
    extern __shared__ float sm[];
    float* Qt  = sm;                                   // [128][68] prologue only
    float* Kt  = sm + 8704;                            // [key][68]
    float* Vt  = sm + 13056;                           // [d][68]
    float* Psw = sm + (threadIdx.x >> 5) * 1088;       // overlay: warp rows of Qt

    const int tid = threadIdx.x, warp = tid >> 5, lane = tid & 31;
    const int gid = lane >> 2, tg = lane & 3;
    const int q0  = blockIdx.x * 128;
    const int bcn = blockIdx.y;
    const int bc  = bcn >> 3, nh = bcn & 7;

    const float* QTb = g_QT + (size_t)bc * BCSTRIDE + nh * 64;              // [w][64]
    const float* Pb  = g_P  + (size_t)bc * BCSTRIDE + (size_t)nh * 64 * W_DIM; // [d][w]

    const unsigned smemB = (unsigned)__cvta_generic_to_shared(sm);
    const unsigned QtB = smemB;
    const unsigned KtB = smemB + 8704u * 4u;
    const unsigned VtB = smemB + 13056u * 4u;
    const unsigned PswB = smemB + (unsigned)(warp * 1088 * 4);

    // per-lane ldmatrix row-address offsets (bytes)
    const int mI = lane >> 3, rI = lane & 7;
    const unsigned kvoff = (unsigned)(((((mI >> 1) * 8) + rI) * 68 + (mI & 1) * 4) * 4);
    const unsigned paoff = (unsigned)(((((mI & 1) * 8) + rI) * 68 + (mI >> 1) * 4) * 4);

    // ---- stage Q tile [q][68] (pure copy; operands pre-tf32) ----
#pragma unroll
    for (int j = 0; j < 8; j++) {
        int i = tid + 256 * j;
        cp_async16(&Qt[(i >> 4) * 68 + (i & 15) * 4],
                   &QTb[(size_t)(q0 + (i >> 4)) * F_DIM + (i & 15) * 4]);
    }
    CP_COMMIT();
    CP_WAIT0();
    __syncthreads();   // FIX: cross-warp cp.async visibility before fragment loads

    // Q a-fragments resident (warp reads ONLY its own 16 rows = its Psw overlay)
    unsigned qa[8][4];
#pragma unroll
    for (int c = 0; c < 8; c++)
        ldsm4(qa[c][0], qa[c][1], qa[c][2], qa[c][3],
              QtB + (unsigned)(warp * 16 * 68 * 4) + paoff + c * 32);

    float o[8][4];
#pragma unroll
    for (int nt = 0; nt < 8; nt++)
#pragma unroll
        for (int j = 0; j < 4; j++) o[nt][j] = 0.f;
    float m0 = -1e30f, m1 = -1e30f, l0 = 0.f, l1 = 0.f;

    for (int kt = 0; kt < 16; kt++) {
        const int k0 = kt * 64;
        __syncthreads();   // prior tile's Kt/Vt reads complete; qa loads done
#pragma unroll
        for (int j = 0; j < 4; j++) {
            int i = tid + 256 * j;
            cp_async16(&Kt[(i >> 4) * 68 + (i & 15) * 4],
                       &QTb[(size_t)(k0 + (i >> 4)) * F_DIM + (i & 15) * 4]);
            cp_async16(&Vt[(i >> 4) * 68 + (i & 15) * 4],
                       &Pb[(size_t)(i >> 4) * W_DIM + k0 + (i & 15) * 4]);
        }
        CP_COMMIT();
        CP_WAIT0();
        __syncthreads();

        // ---- S = Q K^T ----
        float s[8][4];
#pragma unroll
        for (int nt = 0; nt < 8; nt++)
#pragma unroll
            for (int j = 0; j < 4; j++) s[nt][j] = 0.f;
#pragma unroll
        for (int ntp = 0; ntp < 4; ntp++) {
            const unsigned kb = KtB + kvoff + (unsigned)(ntp * 16 * 68 * 4);
#pragma unroll
            for (int c = 0; c < 8; c++) {
                unsigned b0, b1, b2, b3;
                ldsm4(b0, b1, b2, b3, kb + c * 32);
                mma_tf32(s[2 * ntp],     qa[c][0], qa[c][1], qa[c][2], qa[c][3], b0, b1);
                mma_tf32(s[2 * ntp + 1], qa[c][0], qa[c][1], qa[c][2], qa[c][3], b2, b3);
            }
        }
        // scale into log2 domain
#pragma unroll
        for (int nt = 0; nt < 8; nt++) {
            s[nt][0] *= SCL2; s[nt][1] *= SCL2; s[nt][2] *= SCL2; s[nt][3] *= SCL2;
        }

        // ---- online softmax (rows gid, gid+8) ----
        float mx0 = -1e30f, mx1 = -1e30f;
#pragma unroll
        for (int nt = 0; nt < 8; nt++) {
            mx0 = fmaxf(mx0, fmaxf(s[nt][0], s[nt][1]));
            mx1 = fmaxf(mx1, fmaxf(s[nt][2], s[nt][3]));
        }
        mx0 = fmaxf(mx0, __shfl_xor_sync(0xffffffffu, mx0, 1));
        mx0 = fmaxf(mx0, __shfl_xor_sync(0xffffffffu, mx0, 2));
        mx1 = fmaxf(mx1, __shfl_xor_sync(0xffffffffu, mx1, 1));
        mx1 = fmaxf(mx1, __shfl_xor_sync(0xffffffffu, mx1, 2));
        float mn0 = fmaxf(m0, mx0), mn1 = fmaxf(m1, mx1);
        float al0 = exp2f(m0 - mn0), al1 = exp2f(m1 - mn1);
        m0 = mn0; m1 = mn1;

        float ps0 = 0.f, ps1 = 0.f;
#pragma unroll
        for (int nt = 0; nt < 8; nt++) {
            float p00 = exp2f(s[nt][0] - mn0);
            float p01 = exp2f(s[nt][1] - mn0);
            float p10 = exp2f(s[nt][2] - mn1);
            float p11 = exp2f(s[nt][3] - mn1);
            ps0 += p00 + p01; ps1 += p10 + p11;
            *(float2*)&Psw[gid * 68 + nt * 8 + 2 * tg] =
                make_float2(f2tf(p00), f2tf(p01));
            *(float2*)&Psw[(gid + 8) * 68 + nt * 8 + 2 * tg] =
                make_float2(f2tf(p10), f2tf(p11));
        }
        l0 = l0 * al0 + ps0;
        l1 = l1 * al1 + ps1;
#pragma unroll
        for (int nt = 0; nt < 8; nt++) {
            o[nt][0] *= al0; o[nt][1] *= al0; o[nt][2] *= al1; o[nt][3] *= al1;
        }
        __syncwarp();   // Psw is warp-private: warp-level sync suffices

        // ---- O += P V ----
#pragma unroll
        for (int c = 0; c < 8; c++) {
            unsigned pa0, pa1, pa2, pa3;
            ldsm4(pa0, pa1, pa2, pa3, PswB + paoff + c * 32);
#pragma unroll
            for (int ntp = 0; ntp < 4; ntp++) {
                unsigned v0, v1, v2, v3;
                ldsm4(v0, v1, v2, v3, VtB + kvoff + (unsigned)(ntp * 16 * 68 * 4) + c * 32);
                mma_tf32(o[2 * ntp],     pa0, pa1, pa2, pa3, v0, v1);
                mma_tf32(o[2 * ntp + 1], pa0, pa1, pa2, pa3, v2, v3);
            }
        }
        __syncwarp();   // Psw rewritten next tile
    }

    // ---- epilogue: normalize, stage in Psw, write g_A[bc][w][h] tf32 ----
    l0 += __shfl_xor_sync(0xffffffffu, l0, 1);
    l0 += __shfl_xor_sync(0xffffffffu, l0, 2);
    l1 += __shfl_xor_sync(0xffffffffu, l1, 1);
    l1 += __shfl_xor_sync(0xffffffffu, l1, 2);
    float inv0 = 1.f / l0, inv1 = 1.f / l1;
#pragma unroll
    for (int nt = 0; nt < 8; nt++) {
        *(float2*)&Psw[gid * 68 + nt * 8 + 2 * tg] =
            make_float2(o[nt][0] * inv0, o[nt][1] * inv0);
        *(float2*)&Psw[(gid + 8) * 68 + nt * 8 + 2 * tg] =
            make_float2(o[nt][2] * inv1, o[nt][3] * inv1);
    }
    __syncwarp();
    float* Ab2 = g_A + (size_t)bc * BCSTRIDE + nh * 64;
#pragma unroll
    for (int i = 0; i < 16; i++) {
        float2 v = *(float2*)&Psw[i * 68 + 2 * lane];
        v.x = f2tf(v.x); v.y = f2tf(v.y);
        *(float2*)&Ab2[(size_t)(q0 + warp * 16 + i) * F_DIM + 2 * lane] = v;
    }
}

// ---------------------------------------------------------------------------
// Launch. Inputs: x, wq, wk, wv, wo, freqs_param (wk/wv dead in reference).
// ---------------------------------------------------------------------------
extern "C" void kernel_launch(void* const* d_in, const int* in_sizes, int n_in,
                              void* d_out, int out_size) {
    (void)in_sizes; (void)n_in; (void)out_size;
    const float* x  = (const float*)d_in[0];
    const float* wq = (const float*)d_in[1];
    const float* wo = (const float*)d_in[4];
    const float* fp = (const float*)d_in[5];
    float* out = (float*)d_out;

    cudaFuncSetAttribute(gemm_tc,     cudaFuncAttributeMaxDynamicSharedMemorySize, 57344);
    cudaFuncSetAttribute(attn_kernel, cudaFuncAttributeMaxDynamicSharedMemorySize, 69632);

    prepw_kernel<<<2048, 256>>>(wq, wo);
    transpose_kernel<<<dim3(32, 16, 8), dim3(32, 8)>>>(x);

    dim3 gg(8, 4, 8);
    gemm_tc<<<gg, 256, 57344>>>(nullptr, fp, 0);     // g_P (tf32) + g_QT (roped, T)
    attn_kernel<<<dim3(8, 64), 256, 69632>>>();      // g_A (transposed, tf32)
    gemm_tc<<<gg, 256, 40960>>>(out, nullptr, 1);    // out = Wo @ A
}